// round 2
// baseline (speedup 1.0000x reference)
#include <cuda_runtime.h>

// GlottalFlowTable — fixed shapes:
//   B=32, S=524288, HOP=256, L=100, frames=2048
//
// R2 strategy: one warp per frame. Both table rows (floor/ceil) live in
// registers (4 per row); random per-sample gathers are resolved with warp
// shuffles instead of scattered LDGs, removing the L1tex wavefront
// bottleneck seen in R1 (L1=64%, DRAM=49%). Fast path (indices < 64,
// always true for this dataset since wp < 0.5) uses 8 SHFL per 32 samples;
// a general 4-way path preserves correctness for arbitrary inputs.

constexpr int B      = 32;
constexpr int S      = 524288;
constexpr int HOP    = 256;
constexpr int L      = 100;
constexpr int FRAMES = S / HOP;    // 2048
constexpr int TROWS  = FRAMES + 1; // 2049

__global__ __launch_bounds__(256)
void glottal_flow_kernel(const float* __restrict__ wp,
                         const float* __restrict__ tables,
                         float* __restrict__ out)
{
    const unsigned FULL = 0xffffffffu;
    int wid  = blockIdx.x * 8 + (threadIdx.x >> 5);  // global warp = (b, frame)
    int lane = threadIdx.x & 31;
    int b    = wid >> 11;          // / FRAMES
    int f    = wid & (FRAMES - 1);

    const float* rowF = tables + (size_t)(b * TROWS + f) * L;
    const float* rowC = rowF + L;

    // Rows into registers: lane holds entries lane, lane+32, lane+64, lane+96
    int i2 = min(lane + 64, L - 1);
    int i3 = min(lane + 96, L - 1);
    float F0 = __ldg(rowF + lane),  F1 = __ldg(rowF + lane + 32);
    float F2 = __ldg(rowF + i2),    F3 = __ldg(rowF + i3);
    float C0 = __ldg(rowC + lane),  C1 = __ldg(rowC + lane + 32);
    float C2 = __ldg(rowC + i2),    C3 = __ldg(rowC + i3);

    const float* wrow = wp  + (size_t)b * S + f * HOP;
    float*       orow = out + (size_t)b * S + f * HOP;

#pragma unroll
    for (int it = 0; it < 8; ++it) {
        int   t       = it * 32 + lane;
        float w       = __ldg(wrow + t);
        float idx_raw = w * (float)L;
        int   fi      = (int)idx_raw;               // trunc toward zero
        fi            = max(0, min(fi, L - 1));     // clip like reference
        float p       = idx_raw - (float)fi;
        int   fj      = fi + 1;
        if (fj == L) fj = 0;                        // padded col L == col 0

        float loF, hiF, loC, hiC;
        if (__all_sync(FULL, (fi | fj) < 64)) {
            // fast path: indices confined to regs {0,1}
            float a0 = __shfl_sync(FULL, F0, fi);
            float a1 = __shfl_sync(FULL, F1, fi);
            float b0 = __shfl_sync(FULL, C0, fi);
            float b1 = __shfl_sync(FULL, C1, fi);
            bool  si = fi >= 32;
            loF = si ? a1 : a0;
            loC = si ? b1 : b0;
            float c0 = __shfl_sync(FULL, F0, fj);
            float c1 = __shfl_sync(FULL, F1, fj);
            float d0 = __shfl_sync(FULL, C0, fj);
            float d1 = __shfl_sync(FULL, C1, fj);
            bool  sj = fj >= 32;
            hiF = sj ? c1 : c0;
            hiC = sj ? d1 : d0;
        } else {
            // general 4-way gather (any index 0..99)
            float a0 = __shfl_sync(FULL, F0, fi);
            float a1 = __shfl_sync(FULL, F1, fi);
            float a2 = __shfl_sync(FULL, F2, fi);
            float a3 = __shfl_sync(FULL, F3, fi);
            float b0 = __shfl_sync(FULL, C0, fi);
            float b1 = __shfl_sync(FULL, C1, fi);
            float b2 = __shfl_sync(FULL, C2, fi);
            float b3 = __shfl_sync(FULL, C3, fi);
            float alo = (fi & 32) ? a1 : a0;
            float ahi = (fi & 32) ? a3 : a2;
            float blo = (fi & 32) ? b1 : b0;
            float bhi = (fi & 32) ? b3 : b2;
            loF = (fi & 64) ? ahi : alo;
            loC = (fi & 64) ? bhi : blo;
            float c0 = __shfl_sync(FULL, F0, fj);
            float c1 = __shfl_sync(FULL, F1, fj);
            float c2 = __shfl_sync(FULL, F2, fj);
            float c3 = __shfl_sync(FULL, F3, fj);
            float d0 = __shfl_sync(FULL, C0, fj);
            float d1 = __shfl_sync(FULL, C1, fj);
            float d2 = __shfl_sync(FULL, C2, fj);
            float d3 = __shfl_sync(FULL, C3, fj);
            float clo = (fj & 32) ? c1 : c0;
            float chi = (fj & 32) ? c3 : c2;
            float dlo = (fj & 32) ? d1 : d0;
            float dhi = (fj & 32) ? d3 : d2;
            hiF = (fj & 64) ? chi : clo;
            hiC = (fj & 64) ? dhi : dlo;
        }

        float vF = fmaf(p, hiF - loF, loF);
        float vC = fmaf(p, hiC - loC, loC);
        float p2 = (float)t * (1.0f / (float)HOP);
        orow[t] = fmaf(p2, vC - vF, vF);
    }
}

extern "C" void kernel_launch(void* const* d_in, const int* in_sizes, int n_in,
                              void* d_out, int out_size)
{
    const float* wp     = (const float*)d_in[0];
    const float* tables = (const float*)d_in[1];
    float*       out    = (float*)d_out;

    constexpr int total_warps = B * FRAMES;        // 65536 warps, 1 per frame
    glottal_flow_kernel<<<total_warps / 8, 256>>>(wp, tables, out);
}

// round 3
// speedup vs baseline: 1.3348x; 1.3348x over previous
#include <cuda_runtime.h>

// GlottalFlowTable — fixed shapes: B=32, S=524288, HOP=256, L=100, frames=2048
//
// R3: one warp per frame. Precompute a per-frame quad table in shared memory:
//   quad[i] = ( loF, dF, loC-loF, dC-dF )  with the wraparound column (L -> 0)
// folded in at build time, so the per-sample inner loop is a single LDS.128
// plus 4 FMAs — no scattered LDGs (R1's L1-wavefront bottleneck) and no
// shuffles (R2's MIO bottleneck). Fully general for any index 0..L-1.
//
//   vF      = loF + p*dF
//   vC - vF = (loC-loF) + p*(dC-dF)
//   out     = vF + p2*(vC - vF)
//           = fmaf(p2, fmaf(p,q.w,q.z), fmaf(p,q.y,q.x))

constexpr int B      = 32;
constexpr int S      = 524288;
constexpr int HOP    = 256;
constexpr int L      = 100;
constexpr int FRAMES = S / HOP;    // 2048
constexpr int TROWS  = FRAMES + 1; // 2049
constexpr int WPB    = 8;          // warps per block

__global__ __launch_bounds__(256)
void glottal_flow_kernel(const float* __restrict__ wp,
                         const float* __restrict__ tables,
                         float* __restrict__ out)
{
    __shared__ float4 quad[WPB][L];   // 8 * 100 * 16B = 12.8 KB

    int warp = threadIdx.x >> 5;
    int lane = threadIdx.x & 31;
    int wid  = blockIdx.x * WPB + warp;       // global warp = (b, frame)
    int b    = wid >> 11;                     // / FRAMES
    int f    = wid & (FRAMES - 1);

    const float* rowF = tables + (size_t)(b * TROWS + f) * L;
    const float* rowC = rowF + L;

    // Build the quad table (wrap column L -> 0 folded in here).
#pragma unroll
    for (int i = lane; i < L; i += 32) {
        int   ip = (i + 1 == L) ? 0 : i + 1;
        float f0 = __ldg(rowF + i);
        float f1 = __ldg(rowF + ip);
        float c0 = __ldg(rowC + i);
        float c1 = __ldg(rowC + ip);
        float dF = f1 - f0;
        float dC = c1 - c0;
        quad[warp][i] = make_float4(f0, dF, c0 - f0, dC - dF);
    }
    __syncwarp();

    const float* wrow = wp  + (size_t)b * S + f * HOP;
    float*       orow = out + (size_t)b * S + f * HOP;

#pragma unroll
    for (int it = 0; it < 8; ++it) {
        int   t       = it * 32 + lane;
        float w       = __ldg(wrow + t);
        float idx_raw = w * (float)L;
        int   fi      = (int)idx_raw;              // trunc toward zero
        fi            = max(0, min(fi, L - 1));    // clip like reference
        float p       = idx_raw - (float)fi;

        float4 q = quad[warp][fi];

        float vF = fmaf(p, q.y, q.x);              // loF + p*dF
        float dV = fmaf(p, q.w, q.z);              // (vC - vF)
        float p2 = (float)t * (1.0f / (float)HOP);
        orow[t] = fmaf(p2, dV, vF);
    }
}

extern "C" void kernel_launch(void* const* d_in, const int* in_sizes, int n_in,
                              void* d_out, int out_size)
{
    const float* wp     = (const float*)d_in[0];
    const float* tables = (const float*)d_in[1];
    float*       out    = (float*)d_out;

    constexpr int total_warps = B * FRAMES;        // 65536 warps, 1 per frame
    glottal_flow_kernel<<<total_warps / WPB, 256>>>(wp, tables, out);
}

// round 4
// speedup vs baseline: 1.4160x; 1.0609x over previous
#include <cuda_runtime.h>

// GlottalFlowTable — fixed shapes: B=32, S=524288, HOP=256, L=100, frames=2048
//
// R4: back to R1's global-gather (cheapest gather: each warp-LDG touches only
// ~2 cache lines of the 400B L1-resident table row), restructured for MLP:
// 8 samples per thread, all 8 phase loads -> all indices -> all 32 gathers
// issued back-to-back -> math -> 2 float4 stores. No reg cap so the gather
// batch stays live (R1's regs=32 forced serialization; issue=46%, nothing
// saturated => latency-bound).

constexpr int B      = 32;
constexpr int S      = 524288;
constexpr int HOP    = 256;
constexpr int L      = 100;
constexpr int FRAMES = S / HOP;    // 2048
constexpr int TROWS  = FRAMES + 1; // 2049
constexpr int S8     = S / 8;      // 65536 8-sample groups per batch row

__global__ void glottal_flow_kernel(const float* __restrict__ wp,
                                    const float* __restrict__ tables,
                                    float* __restrict__ out)
{
    int i8 = blockIdx.x * blockDim.x + threadIdx.x;   // global 8-sample group
    int b  = i8 / S8;
    int s8 = i8 - b * S8;
    int s  = s8 << 3;                 // sample index within batch row
    int f  = s >> 8;                  // frame (HOP=256); 8 | 256 so no straddle
    int t  = s & (HOP - 1);

    const float4* wv = reinterpret_cast<const float4*>(wp) + i8 * 2;
    float4 w0 = wv[0];
    float4 w1 = wv[1];

    const float* rowF = tables + (size_t)(b * TROWS + f) * L;
    const float* rowC = rowF + L;

    float w[8] = {w0.x, w0.y, w0.z, w0.w, w1.x, w1.y, w1.z, w1.w};

    // Phase 1: all indices / fractions (no memory deps)
    int   fi[8], fj[8];
    float p[8];
#pragma unroll
    for (int k = 0; k < 8; ++k) {
        float idx_raw = w[k] * (float)L;
        int   v       = (int)idx_raw;              // trunc toward zero
        v             = max(0, min(v, L - 1));     // clip like reference
        fi[k]         = v;
        p[k]          = idx_raw - (float)v;
        int   u       = v + 1;
        fj[k]         = (u == L) ? 0 : u;          // padded col L == col 0
    }

    // Phase 2: all 32 gathers issued back-to-back (max MLP)
    float loF[8], hiF[8], loC[8], hiC[8];
#pragma unroll
    for (int k = 0; k < 8; ++k) loF[k] = __ldg(rowF + fi[k]);
#pragma unroll
    for (int k = 0; k < 8; ++k) hiF[k] = __ldg(rowF + fj[k]);
#pragma unroll
    for (int k = 0; k < 8; ++k) loC[k] = __ldg(rowC + fi[k]);
#pragma unroll
    for (int k = 0; k < 8; ++k) hiC[k] = __ldg(rowC + fj[k]);

    // Phase 3: math + store
    float r[8];
#pragma unroll
    for (int k = 0; k < 8; ++k) {
        float vF = fmaf(p[k], hiF[k] - loF[k], loF[k]);
        float vC = fmaf(p[k], hiC[k] - loC[k], loC[k]);
        float p2 = (float)(t + k) * (1.0f / (float)HOP);
        r[k] = fmaf(p2, vC - vF, vF);
    }

    float4* ov = reinterpret_cast<float4*>(out) + i8 * 2;
    ov[0] = make_float4(r[0], r[1], r[2], r[3]);
    ov[1] = make_float4(r[4], r[5], r[6], r[7]);
}

extern "C" void kernel_launch(void* const* d_in, const int* in_sizes, int n_in,
                              void* d_out, int out_size)
{
    const float* wp     = (const float*)d_in[0];
    const float* tables = (const float*)d_in[1];
    float*       out    = (float*)d_out;

    constexpr int total8 = (B * S) / 8;            // 2,097,152 groups
    glottal_flow_kernel<<<total8 / 256, 256>>>(wp, tables, out);
}